// round 2
// baseline (speedup 1.0000x reference)
#include <cuda_runtime.h>

#define TTYPES   4
#define DOUT     128
#define FIN      132
#define KIN      128
#define HID      512
#define MTILE    64
#define NTHREADS 256
#define HS_STRIDE 516   // 512 + 4 pad: breaks bank-conflict periodicity

// smem: Xs[64*132] + Hs[64*516] + perm[64] + pbase[64] + stype[64]
#define SMEM_BYTES (((MTILE*FIN) + (MTILE*HS_STRIDE)) * 4 + MTILE * 3 * 4)

__global__ __launch_bounds__(NTHREADS, 1)
void mlp_fused_kernel(const float* __restrict__ nf,
                      const float* __restrict__ W1,
                      const float* __restrict__ b1,
                      const float* __restrict__ W2,
                      const float* __restrict__ b2,
                      float* __restrict__ out,
                      int ntot)
{
    extern __shared__ float smem[];
    float* Xs = smem;                                 // [MTILE][FIN]
    float* Hs = smem + MTILE * FIN;                   // [MTILE][HS_STRIDE]
    int*   perm  = (int*)(Hs + MTILE * HS_STRIDE);    // [MTILE] rows sorted by type
    int*   pbase = perm + MTILE;                      // [MTILE] type*DOUT per perm slot
    int*   stype = pbase + MTILE;                     // [MTILE]

    const int base  = blockIdx.x * MTILE;
    const int tid   = threadIdx.x;
    const int nrows = min(MTILE, ntot - base);

    // ---- Stage input tile (rows are contiguous: straight memcpy) ----
    {
        const float* src = nf + (size_t)base * FIN;
        const int total = nrows * FIN;
        for (int idx = tid; idx < total; idx += NTHREADS)
            Xs[idx] = src[idx];
        for (int idx = total + tid; idx < MTILE * FIN; idx += NTHREADS)
            Xs[idx] = 0.0f;   // pad rows -> finite garbage, stores are guarded
    }
    __syncthreads();

    // ---- Per-row node type: argmax of first 4 features (first-max ties) ----
    if (tid < MTILE) {
        int t = 0;
        float m = Xs[tid * FIN + 0];
        #pragma unroll
        for (int j = 1; j < TTYPES; j++) {
            float v = Xs[tid * FIN + j];
            if (v > m) { m = v; t = j; }
        }
        stype[tid] = t;
    }
    __syncthreads();

    // ---- Counting sort rows by type (serial, ~200 cycles, hidden by GEMM1) ----
    if (tid == 0) {
        int cnt[TTYPES] = {0, 0, 0, 0};
        for (int r = 0; r < MTILE; r++) cnt[stype[r]]++;
        int offs[TTYPES];
        offs[0] = 0;
        #pragma unroll
        for (int t = 1; t < TTYPES; t++) offs[t] = offs[t-1] + cnt[t-1];
        for (int r = 0; r < MTILE; r++) {
            int t = stype[r];
            int p = offs[t]++;
            perm[p]  = r;
            pbase[p] = t * DOUT;
        }
    }
    // (visibility of perm/pbase is covered by the __syncthreads before GEMM2)

    const int ty = tid >> 4;      // 0..15 : 4-row group
    const int tx = tid & 15;      // 0..15 : 8-col group
    const int r0 = ty * 4;

    // =================== GEMM1: H = gelu(X @ W1 + b1) ===================
    const float* x0 = Xs + (r0 + 0) * FIN + TTYPES;
    const float* x1 = Xs + (r0 + 1) * FIN + TTYPES;
    const float* x2 = Xs + (r0 + 2) * FIN + TTYPES;
    const float* x3 = Xs + (r0 + 3) * FIN + TTYPES;

    #pragma unroll 1
    for (int chunk = 0; chunk < 4; chunk++) {
        const int jbase = chunk * 128 + tx * 8;
        const float* w1p = W1 + jbase;

        float acc[4][8];
        #pragma unroll
        for (int i = 0; i < 4; i++)
            #pragma unroll
            for (int m = 0; m < 8; m++) acc[i][m] = 0.0f;

        #pragma unroll 2
        for (int k = 0; k < KIN; k += 4) {
            float4 A0 = *(const float4*)(x0 + k);
            float4 A1 = *(const float4*)(x1 + k);
            float4 A2 = *(const float4*)(x2 + k);
            float4 A3 = *(const float4*)(x3 + k);
            float av[4][4] = {{A0.x, A0.y, A0.z, A0.w},
                              {A1.x, A1.y, A1.z, A1.w},
                              {A2.x, A2.y, A2.z, A2.w},
                              {A3.x, A3.y, A3.z, A3.w}};
            #pragma unroll
            for (int kk = 0; kk < 4; kk++) {
                const float* wrow = w1p + (k + kk) * HID;
                float4 w0 = *(const float4*)(wrow);
                float4 w1v = *(const float4*)(wrow + 4);
                float wv[8] = {w0.x, w0.y, w0.z, w0.w, w1v.x, w1v.y, w1v.z, w1v.w};
                #pragma unroll
                for (int m = 0; m < 8; m++) {
                    acc[0][m] += av[0][kk] * wv[m];
                    acc[1][m] += av[1][kk] * wv[m];
                    acc[2][m] += av[2][kk] * wv[m];
                    acc[3][m] += av[3][kk] * wv[m];
                }
            }
        }

        // bias + exact GELU (x * Phi(x) == jax gelu approximate=False)
        float4 bb0 = *(const float4*)(b1 + jbase);
        float4 bb1 = *(const float4*)(b1 + jbase + 4);
        float bv[8] = {bb0.x, bb0.y, bb0.z, bb0.w, bb1.x, bb1.y, bb1.z, bb1.w};
        #pragma unroll
        for (int i = 0; i < 4; i++) {
            float o[8];
            #pragma unroll
            for (int m = 0; m < 8; m++) {
                float v = acc[i][m] + bv[m];
                o[m] = v * normcdff(v);
            }
            float4* dst = (float4*)(Hs + (r0 + i) * HS_STRIDE + jbase);
            dst[0] = make_float4(o[0], o[1], o[2], o[3]);
            dst[1] = make_float4(o[4], o[5], o[6], o[7]);
        }
    }
    __syncthreads();

    // ====== GEMM2 (pruned): out = H @ W2[:, type*D : type*D+D] + b2 ======
    {
        int rI[4], bI[4];
        const float* hp[4];
        #pragma unroll
        for (int i = 0; i < 4; i++) {
            int p = r0 + i;
            rI[i] = perm[p];
            bI[i] = pbase[p];
            hp[i] = Hs + rI[i] * HS_STRIDE;
        }

        float acc[4][8];
        #pragma unroll
        for (int i = 0; i < 4; i++)
            #pragma unroll
            for (int m = 0; m < 8; m++) acc[i][m] = 0.0f;

        const bool uni = (bI[0] == bI[1]) & (bI[1] == bI[2]) & (bI[2] == bI[3]);

        if (uni) {
            // Fast path (61+/64 rows after counting sort): the whole 4-row
            // group shares one W2 column-block -> ONE weight load per kk.
            // Drops GEMM2 from 8 to 2 LDG.128 per warp per kk; FFMA-limited.
            const float* wp = W2 + bI[0] + tx * 8;
            #pragma unroll 1
            for (int k = 0; k < HID; k += 4) {
                float4 H0 = *(const float4*)(hp[0] + k);
                float4 H1 = *(const float4*)(hp[1] + k);
                float4 H2 = *(const float4*)(hp[2] + k);
                float4 H3 = *(const float4*)(hp[3] + k);
                float hv[4][4] = {{H0.x, H0.y, H0.z, H0.w},
                                  {H1.x, H1.y, H1.z, H1.w},
                                  {H2.x, H2.y, H2.z, H2.w},
                                  {H3.x, H3.y, H3.z, H3.w}};
                #pragma unroll
                for (int kk = 0; kk < 4; kk++) {
                    const float* wrow = wp + (k + kk) * HID;
                    float4 w0 = *(const float4*)(wrow);
                    float4 w1v = *(const float4*)(wrow + 4);
                    float wv[8] = {w0.x, w0.y, w0.z, w0.w,
                                   w1v.x, w1v.y, w1v.z, w1v.w};
                    #pragma unroll
                    for (int m = 0; m < 8; m++) {
                        acc[0][m] += hv[0][kk] * wv[m];
                        acc[1][m] += hv[1][kk] * wv[m];
                        acc[2][m] += hv[2][kk] * wv[m];
                        acc[3][m] += hv[3][kk] * wv[m];
                    }
                }
            }
        } else {
            // Slow path: mixed-type group (<=3 per CTA), per-row weight base.
            const float* wp[4];
            #pragma unroll
            for (int i = 0; i < 4; i++) wp[i] = W2 + bI[i] + tx * 8;
            #pragma unroll 1
            for (int k = 0; k < HID; k += 4) {
                float4 H0 = *(const float4*)(hp[0] + k);
                float4 H1 = *(const float4*)(hp[1] + k);
                float4 H2 = *(const float4*)(hp[2] + k);
                float4 H3 = *(const float4*)(hp[3] + k);
                float hv[4][4] = {{H0.x, H0.y, H0.z, H0.w},
                                  {H1.x, H1.y, H1.z, H1.w},
                                  {H2.x, H2.y, H2.z, H2.w},
                                  {H3.x, H3.y, H3.z, H3.w}};
                #pragma unroll
                for (int kk = 0; kk < 4; kk++) {
                    #pragma unroll
                    for (int i = 0; i < 4; i++) {
                        const float* wrow = wp[i] + (k + kk) * HID;
                        float4 w0 = *(const float4*)(wrow);
                        float4 w1v = *(const float4*)(wrow + 4);
                        float wv[8] = {w0.x, w0.y, w0.z, w0.w,
                                       w1v.x, w1v.y, w1v.z, w1v.w};
                        float a = hv[i][kk];
                        #pragma unroll
                        for (int m = 0; m < 8; m++)
                            acc[i][m] += a * wv[m];
                    }
                }
            }
        }

        // bias + scatter store (row order is permuted; cols coalesced)
        #pragma unroll
        for (int i = 0; i < 4; i++) {
            if (rI[i] < nrows) {
                const float* b2p = b2 + bI[i] + tx * 8;
                float4 bb0 = *(const float4*)(b2p);
                float4 bb1 = *(const float4*)(b2p + 4);
                float4 o0 = make_float4(acc[i][0] + bb0.x, acc[i][1] + bb0.y,
                                        acc[i][2] + bb0.z, acc[i][3] + bb0.w);
                float4 o1 = make_float4(acc[i][4] + bb1.x, acc[i][5] + bb1.y,
                                        acc[i][6] + bb1.z, acc[i][7] + bb1.w);
                float4* dst = (float4*)(out + (size_t)(base + rI[i]) * DOUT + tx * 8);
                dst[0] = o0;
                dst[1] = o1;
            }
        }
    }
}

extern "C" void kernel_launch(void* const* d_in, const int* in_sizes, int n_in,
                              void* d_out, int out_size)
{
    const float* nf = (const float*)d_in[0];
    const float* W1 = (const float*)d_in[1];
    const float* b1 = (const float*)d_in[2];
    const float* W2 = (const float*)d_in[3];
    const float* b2 = (const float*)d_in[4];
    float* out = (float*)d_out;

    const int ntot = in_sizes[0] / FIN;
    const int grid = (ntot + MTILE - 1) / MTILE;

    cudaFuncSetAttribute(mlp_fused_kernel,
                         cudaFuncAttributeMaxDynamicSharedMemorySize, SMEM_BYTES);
    mlp_fused_kernel<<<grid, NTHREADS, SMEM_BYTES>>>(nf, W1, b1, W2, b2, out, ntot);
}

// round 3
// speedup vs baseline: 1.1460x; 1.1460x over previous
#include <cuda_runtime.h>

#define TTYPES   4
#define DOUT     128
#define FIN      132
#define KIN      128
#define HID      512
#define CHUNK    128            // GEMM1 N-chunk == GEMM2 K-chunk
#define NCHUNKS  (HID / CHUNK)  // 4
#define MTILE    64
#define NTHREADS 256
#define HC_STRIDE 132           // 128 + 4 pad: de-periodize banks

// smem: Xs[64*132] + Hc[64*132] + perm[64] + pbase[64] + stype[64]
#define SMEM_BYTES ((MTILE*FIN + MTILE*HC_STRIDE) * 4 + MTILE * 3 * 4)

__global__ __launch_bounds__(NTHREADS, 2)   // force <=128 regs -> 2 CTAs/SM
void mlp_fused_kernel(const float* __restrict__ nf,
                      const float* __restrict__ W1,
                      const float* __restrict__ b1,
                      const float* __restrict__ W2,
                      const float* __restrict__ b2,
                      float* __restrict__ out,
                      int ntot)
{
    extern __shared__ float smem[];
    float* Xs = smem;                                 // [MTILE][FIN]
    float* Hc = smem + MTILE * FIN;                   // [MTILE][HC_STRIDE] (one chunk)
    int*   perm  = (int*)(Hc + MTILE * HC_STRIDE);    // [MTILE]
    int*   pbase = perm + MTILE;                      // [MTILE]
    int*   stype = pbase + MTILE;                     // [MTILE]

    const int base  = blockIdx.x * MTILE;
    const int tid   = threadIdx.x;
    const int nrows = min(MTILE, ntot - base);

    // ---- Stage input tile ----
    {
        const float* src = nf + (size_t)base * FIN;
        const int total = nrows * FIN;
        for (int idx = tid; idx < total; idx += NTHREADS)
            Xs[idx] = src[idx];
        for (int idx = total + tid; idx < MTILE * FIN; idx += NTHREADS)
            Xs[idx] = 0.0f;   // pad rows finite; their stores are guarded
    }
    __syncthreads();

    // ---- node type: argmax of first 4 feats (first-max ties, jnp semantics) ----
    if (tid < MTILE) {
        int t = 0;
        float m = Xs[tid * FIN + 0];
        #pragma unroll
        for (int j = 1; j < TTYPES; j++) {
            float v = Xs[tid * FIN + j];
            if (v > m) { m = v; t = j; }
        }
        stype[tid] = t;
    }
    __syncthreads();

    // ---- counting sort rows by type -> type-uniform 4-row groups ----
    if (tid == 0) {
        int cnt[TTYPES] = {0, 0, 0, 0};
        for (int r = 0; r < MTILE; r++) cnt[stype[r]]++;
        int offs[TTYPES];
        offs[0] = 0;
        #pragma unroll
        for (int t = 1; t < TTYPES; t++) offs[t] = offs[t-1] + cnt[t-1];
        for (int r = 0; r < MTILE; r++) {
            int t = stype[r];
            int p = offs[t]++;
            perm[p]  = r;
            pbase[p] = t * DOUT;
        }
    }
    __syncthreads();   // perm/pbase visible to everyone before chunk loop

    const int ty = tid >> 4;      // 0..15 : 4-row group
    const int tx = tid & 15;      // 0..15 : 8-col group
    const int r0 = ty * 4;

    // GEMM2 row bookkeeping (permuted rows, pruned W2 block)
    int rI[4], bI[4];
    const float* hp[4];
    #pragma unroll
    for (int i = 0; i < 4; i++) {
        int p = r0 + i;
        rI[i] = perm[p];
        bI[i] = pbase[p];
        hp[i] = Hc + rI[i] * HC_STRIDE;
    }
    const bool uni = (bI[0] == bI[1]) & (bI[1] == bI[2]) & (bI[2] == bI[3]);

    // persistent output accumulators (final 64x128 tile)
    float acc2[4][8];
    #pragma unroll
    for (int i = 0; i < 4; i++)
        #pragma unroll
        for (int m = 0; m < 8; m++) acc2[i][m] = 0.0f;

    const float* x0 = Xs + (r0 + 0) * FIN + TTYPES;
    const float* x1 = Xs + (r0 + 1) * FIN + TTYPES;
    const float* x2 = Xs + (r0 + 2) * FIN + TTYPES;
    const float* x3 = Xs + (r0 + 3) * FIN + TTYPES;

    // ============ chunked fusion: H never fully materialized ============
    #pragma unroll 1
    for (int chunk = 0; chunk < NCHUNKS; chunk++) {
        // ---- GEMM1 chunk: Hc = gelu(X @ W1[:, c*128 .. c*128+128) + b1) ----
        const int jb = chunk * CHUNK + tx * 8;
        {
            float acc1[4][8];
            #pragma unroll
            for (int i = 0; i < 4; i++)
                #pragma unroll
                for (int m = 0; m < 8; m++) acc1[i][m] = 0.0f;

            const float* w1p = W1 + jb;
            #pragma unroll 1
            for (int k = 0; k < KIN; k += 4) {
                float4 A0 = *(const float4*)(x0 + k);
                float4 A1 = *(const float4*)(x1 + k);
                float4 A2 = *(const float4*)(x2 + k);
                float4 A3 = *(const float4*)(x3 + k);
                float av[4][4] = {{A0.x, A0.y, A0.z, A0.w},
                                  {A1.x, A1.y, A1.z, A1.w},
                                  {A2.x, A2.y, A2.z, A2.w},
                                  {A3.x, A3.y, A3.z, A3.w}};
                #pragma unroll
                for (int kk = 0; kk < 4; kk++) {
                    const float* wrow = w1p + (k + kk) * HID;
                    float4 w0  = *(const float4*)(wrow);
                    float4 w1v = *(const float4*)(wrow + 4);
                    float wv[8] = {w0.x, w0.y, w0.z, w0.w,
                                   w1v.x, w1v.y, w1v.z, w1v.w};
                    #pragma unroll
                    for (int m = 0; m < 8; m++) {
                        acc1[0][m] += av[0][kk] * wv[m];
                        acc1[1][m] += av[1][kk] * wv[m];
                        acc1[2][m] += av[2][kk] * wv[m];
                        acc1[3][m] += av[3][kk] * wv[m];
                    }
                }
            }

            // bias + exact GELU (x * Phi(x) == jax approximate=False)
            float4 bb0 = *(const float4*)(b1 + jb);
            float4 bb1 = *(const float4*)(b1 + jb + 4);
            float bv[8] = {bb0.x, bb0.y, bb0.z, bb0.w,
                           bb1.x, bb1.y, bb1.z, bb1.w};
            #pragma unroll
            for (int i = 0; i < 4; i++) {
                float o[8];
                #pragma unroll
                for (int m = 0; m < 8; m++) {
                    float v = acc1[i][m] + bv[m];
                    o[m] = v * normcdff(v);
                }
                float4* dst = (float4*)(Hc + (r0 + i) * HC_STRIDE + tx * 8);
                dst[0] = make_float4(o[0], o[1], o[2], o[3]);
                dst[1] = make_float4(o[4], o[5], o[6], o[7]);
            }
        }
        __syncthreads();   // Hc chunk complete

        // ---- GEMM2 partial: acc2 += Hc @ W2[c*128 .. , selected 128 cols] ----
        if (uni) {
            // type-uniform group (61+/64 rows): one weight load per kk
            const float* wk = W2 + (size_t)chunk * CHUNK * HID + bI[0] + tx * 8;
            #pragma unroll 1
            for (int k = 0; k < CHUNK; k += 4) {
                float4 H0 = *(const float4*)(hp[0] + k);
                float4 H1 = *(const float4*)(hp[1] + k);
                float4 H2 = *(const float4*)(hp[2] + k);
                float4 H3 = *(const float4*)(hp[3] + k);
                float hv[4][4] = {{H0.x, H0.y, H0.z, H0.w},
                                  {H1.x, H1.y, H1.z, H1.w},
                                  {H2.x, H2.y, H2.z, H2.w},
                                  {H3.x, H3.y, H3.z, H3.w}};
                #pragma unroll
                for (int kk = 0; kk < 4; kk++) {
                    float4 w0  = *(const float4*)(wk);
                    float4 w1v = *(const float4*)(wk + 4);
                    wk += HID;
                    float wv[8] = {w0.x, w0.y, w0.z, w0.w,
                                   w1v.x, w1v.y, w1v.z, w1v.w};
                    #pragma unroll
                    for (int m = 0; m < 8; m++) {
                        acc2[0][m] += hv[0][kk] * wv[m];
                        acc2[1][m] += hv[1][kk] * wv[m];
                        acc2[2][m] += hv[2][kk] * wv[m];
                        acc2[3][m] += hv[3][kk] * wv[m];
                    }
                }
            }
        } else {
            // mixed-type boundary group (<=3 per CTA)
            const float* wp[4];
            #pragma unroll
            for (int i = 0; i < 4; i++)
                wp[i] = W2 + (size_t)chunk * CHUNK * HID + bI[i] + tx * 8;
            #pragma unroll 1
            for (int k = 0; k < CHUNK; k += 4) {
                float4 H0 = *(const float4*)(hp[0] + k);
                float4 H1 = *(const float4*)(hp[1] + k);
                float4 H2 = *(const float4*)(hp[2] + k);
                float4 H3 = *(const float4*)(hp[3] + k);
                float hv[4][4] = {{H0.x, H0.y, H0.z, H0.w},
                                  {H1.x, H1.y, H1.z, H1.w},
                                  {H2.x, H2.y, H2.z, H2.w},
                                  {H3.x, H3.y, H3.z, H3.w}};
                #pragma unroll
                for (int kk = 0; kk < 4; kk++) {
                    #pragma unroll
                    for (int i = 0; i < 4; i++) {
                        const float* wrow = wp[i] + (k + kk) * HID;
                        float4 w0  = *(const float4*)(wrow);
                        float4 w1v = *(const float4*)(wrow + 4);
                        float wv[8] = {w0.x, w0.y, w0.z, w0.w,
                                       w1v.x, w1v.y, w1v.z, w1v.w};
                        float a = hv[i][kk];
                        #pragma unroll
                        for (int m = 0; m < 8; m++)
                            acc2[i][m] += a * wv[m];
                    }
                }
            }
        }
        __syncthreads();   // done reading Hc before next chunk overwrites
    }

    // ---- bias + scatter store (rows permuted, cols coalesced float4) ----
    #pragma unroll
    for (int i = 0; i < 4; i++) {
        if (rI[i] < nrows) {
            const float* b2p = b2 + bI[i] + tx * 8;
            float4 bb0 = *(const float4*)(b2p);
            float4 bb1 = *(const float4*)(b2p + 4);
            float4 o0 = make_float4(acc2[i][0] + bb0.x, acc2[i][1] + bb0.y,
                                    acc2[i][2] + bb0.z, acc2[i][3] + bb0.w);
            float4 o1 = make_float4(acc2[i][4] + bb1.x, acc2[i][5] + bb1.y,
                                    acc2[i][6] + bb1.z, acc2[i][7] + bb1.w);
            float4* dst = (float4*)(out + (size_t)(base + rI[i]) * DOUT + tx * 8);
            dst[0] = o0;
            dst[1] = o1;
        }
    }
}

extern "C" void kernel_launch(void* const* d_in, const int* in_sizes, int n_in,
                              void* d_out, int out_size)
{
    const float* nf = (const float*)d_in[0];
    const float* W1 = (const float*)d_in[1];
    const float* b1 = (const float*)d_in[2];
    const float* W2 = (const float*)d_in[3];
    const float* b2 = (const float*)d_in[4];
    float* out = (float*)d_out;

    const int ntot = in_sizes[0] / FIN;
    const int grid = (ntot + MTILE - 1) / MTILE;

    cudaFuncSetAttribute(mlp_fused_kernel,
                         cudaFuncAttributeMaxDynamicSharedMemorySize, SMEM_BYTES);
    mlp_fused_kernel<<<grid, NTHREADS, SMEM_BYTES>>>(nf, W1, b1, W2, b2, out, ntot);
}

// round 4
// speedup vs baseline: 1.4471x; 1.2628x over previous
#include <cuda_runtime.h>

#define TTYPES   4
#define DOUT     128
#define KIN      128
#define FIN      132
#define HID      512
#define CHUNK    128            // GEMM1 N-chunk == GEMM2 K-chunk
#define NCHUNKS  (HID / CHUNK)  // 4
#define MTILE    64
#define NTHREADS 256
#define HC_STRIDE 132

// smem: Xs[64*132] + Hc[64*132] + perm/pbase/stype
#define SMEM_BYTES ((MTILE*FIN + MTILE*HC_STRIDE) * 4 + MTILE * 3 * 4)

__global__ __launch_bounds__(NTHREADS, 2)
void mlp_fused_kernel(const float* __restrict__ nf,
                      const float* __restrict__ W1,
                      const float* __restrict__ b1,
                      const float* __restrict__ W2,
                      const float* __restrict__ b2,
                      float* __restrict__ out,
                      int ntot)
{
    extern __shared__ float smem[];
    float* Xs = smem;                                 // [MTILE][FIN]
    float* Hc = smem + MTILE * FIN;                   // [MTILE][HC_STRIDE]
    int*   perm  = (int*)(Hc + MTILE * HC_STRIDE);
    int*   pbase = perm + MTILE;
    int*   stype = pbase + MTILE;

    const int base  = blockIdx.x * MTILE;
    const int tid   = threadIdx.x;
    const int nrows = min(MTILE, ntot - base);

    // ---- stage input tile ----
    {
        const float* src = nf + (size_t)base * FIN;
        const int total = nrows * FIN;
        for (int idx = tid; idx < total; idx += NTHREADS)
            Xs[idx] = src[idx];
        for (int idx = total + tid; idx < MTILE * FIN; idx += NTHREADS)
            Xs[idx] = 0.0f;
    }
    __syncthreads();

    // ---- node type (argmax of first 4, first-max ties) ----
    if (tid < MTILE) {
        int t = 0;
        float m = Xs[tid * FIN + 0];
        #pragma unroll
        for (int j = 1; j < TTYPES; j++) {
            float v = Xs[tid * FIN + j];
            if (v > m) { m = v; t = j; }
        }
        stype[tid] = t;
    }
    __syncthreads();

    // ---- counting sort rows by type ----
    if (tid == 0) {
        int cnt[TTYPES] = {0, 0, 0, 0};
        for (int r = 0; r < MTILE; r++) cnt[stype[r]]++;
        int offs[TTYPES];
        offs[0] = 0;
        #pragma unroll
        for (int t = 1; t < TTYPES; t++) offs[t] = offs[t-1] + cnt[t-1];
        for (int r = 0; r < MTILE; r++) {
            int t = stype[r];
            int p = offs[t]++;
            perm[p]  = r;
            pbase[p] = t * DOUT;
        }
    }
    __syncthreads();

    // 8 rows x 4 cols per thread:
    //   warp = one 8-row group (A-operands broadcast across the warp)
    //   tx 0..31 covers all 128 chunk columns (one float4 each)
    const int ty = tid >> 5;      // 0..7
    const int tx = tid & 31;      // 0..31
    const int r0 = ty * 8;

    int rI[8], bI[8];
    #pragma unroll
    for (int i = 0; i < 8; i++) {
        rI[i] = perm[r0 + i];
        bI[i] = pbase[r0 + i];
    }
    bool uni = true;
    #pragma unroll
    for (int i = 1; i < 8; i++) uni &= (bI[i] == bI[0]);

    // persistent GEMM2 accumulators: 8 rows x 4 cols
    float4 acc2[8];
    #pragma unroll
    for (int i = 0; i < 8; i++) acc2[i] = make_float4(0.f, 0.f, 0.f, 0.f);

    #pragma unroll 1
    for (int chunk = 0; chunk < NCHUNKS; chunk++) {
        const int jb = chunk * CHUNK + tx * 4;

        // ---- GEMM1 chunk: Hc = gelu(X @ W1[:, chunk] + b1) ----
        {
            float4 acc1[8];
            #pragma unroll
            for (int i = 0; i < 8; i++) acc1[i] = make_float4(0.f, 0.f, 0.f, 0.f);

            const float* w1p = W1 + jb;
            #pragma unroll 1
            for (int k = 0; k < KIN; k += 4) {
                // A: 8 rows x 4 k (warp-broadcast LDS.128)
                float4 a[8];
                #pragma unroll
                for (int i = 0; i < 8; i++)
                    a[i] = *(const float4*)(Xs + (r0 + i) * FIN + TTYPES + k);
                #pragma unroll
                for (int kk = 0; kk < 4; kk++) {
                    float4 w = *(const float4*)(w1p + (k + kk) * HID);
                    float av[8] = {(&a[0].x)[kk], (&a[1].x)[kk],
                                   (&a[2].x)[kk], (&a[3].x)[kk],
                                   (&a[4].x)[kk], (&a[5].x)[kk],
                                   (&a[6].x)[kk], (&a[7].x)[kk]};
                    #pragma unroll
                    for (int i = 0; i < 8; i++) {
                        acc1[i].x += av[i] * w.x;
                        acc1[i].y += av[i] * w.y;
                        acc1[i].z += av[i] * w.z;
                        acc1[i].w += av[i] * w.w;
                    }
                }
            }

            float4 bb = *(const float4*)(b1 + jb);
            #pragma unroll
            for (int i = 0; i < 8; i++) {
                float v0 = acc1[i].x + bb.x;
                float v1 = acc1[i].y + bb.y;
                float v2 = acc1[i].z + bb.z;
                float v3 = acc1[i].w + bb.w;
                // exact GELU: x * Phi(x) (jax approximate=False)
                float4 o = make_float4(v0 * normcdff(v0), v1 * normcdff(v1),
                                       v2 * normcdff(v2), v3 * normcdff(v3));
                *(float4*)(Hc + (r0 + i) * HC_STRIDE + tx * 4) = o;
            }
        }
        __syncthreads();   // Hc chunk complete

        // ---- GEMM2 partial: acc2 += Hc(perm rows) @ W2[chunk rows, type cols] ----
        const size_t wbase = (size_t)chunk * CHUNK * HID;
        if (uni) {
            const float* wk = W2 + wbase + bI[0] + tx * 4;
            #pragma unroll 1
            for (int k = 0; k < CHUNK; k += 4) {
                float4 h[8];
                #pragma unroll
                for (int i = 0; i < 8; i++)
                    h[i] = *(const float4*)(Hc + rI[i] * HC_STRIDE + k);
                #pragma unroll
                for (int kk = 0; kk < 4; kk++) {
                    float4 w = *(const float4*)(wk);
                    wk += HID;
                    float hv[8] = {(&h[0].x)[kk], (&h[1].x)[kk],
                                   (&h[2].x)[kk], (&h[3].x)[kk],
                                   (&h[4].x)[kk], (&h[5].x)[kk],
                                   (&h[6].x)[kk], (&h[7].x)[kk]};
                    #pragma unroll
                    for (int i = 0; i < 8; i++) {
                        acc2[i].x += hv[i] * w.x;
                        acc2[i].y += hv[i] * w.y;
                        acc2[i].z += hv[i] * w.z;
                        acc2[i].w += hv[i] * w.w;
                    }
                }
            }
        } else {
            // mixed-type boundary group (<=3 of 8 per CTA): per-row weights
            #pragma unroll 1
            for (int k = 0; k < CHUNK; k += 4) {
                float4 h[8];
                #pragma unroll
                for (int i = 0; i < 8; i++)
                    h[i] = *(const float4*)(Hc + rI[i] * HC_STRIDE + k);
                #pragma unroll
                for (int kk = 0; kk < 4; kk++) {
                    const float* wrow = W2 + wbase + (size_t)(k + kk) * HID + tx * 4;
                    #pragma unroll
                    for (int i = 0; i < 8; i++) {
                        float4 w = *(const float4*)(wrow + bI[i]);
                        float a = (&h[i].x)[kk];
                        acc2[i].x += a * w.x;
                        acc2[i].y += a * w.y;
                        acc2[i].z += a * w.z;
                        acc2[i].w += a * w.w;
                    }
                }
            }
        }
        __syncthreads();   // done reading Hc before next chunk overwrites
    }

    // ---- bias + scatter store (full 128-col row per warp: coalesced) ----
    #pragma unroll
    for (int i = 0; i < 8; i++) {
        if (rI[i] < nrows) {
            float4 bb = *(const float4*)(b2 + bI[i] + tx * 4);
            float4 o = make_float4(acc2[i].x + bb.x, acc2[i].y + bb.y,
                                   acc2[i].z + bb.z, acc2[i].w + bb.w);
            *(float4*)(out + (size_t)(base + rI[i]) * DOUT + tx * 4) = o;
        }
    }
}

extern "C" void kernel_launch(void* const* d_in, const int* in_sizes, int n_in,
                              void* d_out, int out_size)
{
    const float* nf = (const float*)d_in[0];
    const float* W1 = (const float*)d_in[1];
    const float* b1 = (const float*)d_in[2];
    const float* W2 = (const float*)d_in[3];
    const float* b2 = (const float*)d_in[4];
    float* out = (float*)d_out;

    const int ntot = in_sizes[0] / FIN;
    const int grid = (ntot + MTILE - 1) / MTILE;

    cudaFuncSetAttribute(mlp_fused_kernel,
                         cudaFuncAttributeMaxDynamicSharedMemorySize, SMEM_BYTES);
    mlp_fused_kernel<<<grid, NTHREADS, SMEM_BYTES>>>(nf, W1, b1, W2, b2, out, ntot);
}

// round 7
// speedup vs baseline: 4.1266x; 2.8517x over previous
#include <cuda_runtime.h>
#include <cuda_bf16.h>
#include <stdint.h>

#define TTYPES   4
#define D_OUT    128
#define FIN      132
#define HID      512
#define MROWS    128
#define NTHREADS 256
#define BUCKET_CAP 262144

#define TW        68            // words per tile row (136 bf16 = 128 + 8 pad)
#define TILE_ELEM 17408         // 128 * 136 bf16 per tile
#define TILE_B    34816         // bytes per tile

// ---------------- device scratch (static: allocation-free) ----------------
__device__ __nv_bfloat16 g_w1t_hi[4 * TILE_ELEM];
__device__ __nv_bfloat16 g_w1t_lo[4 * TILE_ELEM];
__device__ __nv_bfloat16 g_w2t_hi[16 * TILE_ELEM];
__device__ __nv_bfloat16 g_w2t_lo[16 * TILE_ELEM];
__device__ int g_counts[TTYPES];
__device__ int g_idx[TTYPES * BUCKET_CAP];

// ---------------- smem layout (bytes) ----------------
#define SM_GIDX  0                       // 128 ints (512 B)
#define SM_X_HI  512
#define SM_X_LO  (SM_X_HI + TILE_B)
#define SM_W_HI  (SM_X_LO + TILE_B)
#define SM_W_LO  (SM_W_HI + TILE_B)
#define SM_H_HI  (SM_W_LO + TILE_B)
#define SM_H_LO  (SM_H_HI + TILE_B)
#define SM_TOTAL (SM_H_LO + TILE_B)      // 209408 B < 227 KB cap

// ---------------- helpers ----------------
__device__ __forceinline__ void mma_bf16(float* c, const uint32_t* a, const uint32_t* b) {
    asm volatile(
        "mma.sync.aligned.m16n8k16.row.col.f32.bf16.bf16.f32 "
        "{%0,%1,%2,%3}, {%4,%5,%6,%7}, {%8,%9}, {%0,%1,%2,%3};"
        : "+f"(c[0]), "+f"(c[1]), "+f"(c[2]), "+f"(c[3])
        : "r"(a[0]), "r"(a[1]), "r"(a[2]), "r"(a[3]), "r"(b[0]), "r"(b[1]));
}
__device__ __forceinline__ uint32_t smem_u32(const void* p) {
    uint32_t a;
    asm("{ .reg .u64 t; cvta.to.shared.u64 t, %1; cvt.u32.u64 %0, t; }"
        : "=r"(a) : "l"(p));
    return a;
}
__device__ __forceinline__ void cpa16(uint32_t s, const void* g) {
    asm volatile("cp.async.cg.shared.global [%0], [%1], 16;" :: "r"(s), "l"(g));
}
#define CPA_COMMIT_WAIT() do { \
    asm volatile("cp.async.commit_group;" ::: "memory"); \
    asm volatile("cp.async.wait_group 0;" ::: "memory"); } while (0)

__device__ __forceinline__ void split_bf16(float v, unsigned short& h, unsigned short& l) {
    __nv_bfloat16 hb = __float2bfloat16(v);
    h = __bfloat16_as_ushort(hb);
    l = __bfloat16_as_ushort(__float2bfloat16(v - __bfloat162float(hb)));
}
__device__ __forceinline__ uint32_t pack_hi(float a, float b) {
    unsigned short ha, la, hb, lb;
    split_bf16(a, ha, la); split_bf16(b, hb, lb);
    return (uint32_t)ha | ((uint32_t)hb << 16);
}
__device__ __forceinline__ void pack2(float a, float b, uint32_t& hi, uint32_t& lo) {
    unsigned short ha, la, hb, lb;
    split_bf16(a, ha, la); split_bf16(b, hb, lb);
    hi = (uint32_t)ha | ((uint32_t)hb << 16);
    lo = (uint32_t)la | ((uint32_t)lb << 16);
}

// ---------------- kernel 0: zero counters ----------------
__global__ void zero_kernel() {
    if (threadIdx.x < TTYPES) g_counts[threadIdx.x] = 0;
}

// ---------------- kernel 1: bucket nodes by argmax type ----------------
__global__ void bucket_kernel(const float* __restrict__ nf, int ntot) {
    int i = blockIdx.x * blockDim.x + threadIdx.x;
    bool v = i < ntot;
    int ty = 0;
    if (v) {
        float4 f = *(const float4*)(nf + (size_t)i * FIN);
        float m = f.x;
        if (f.y > m) { m = f.y; ty = 1; }
        if (f.z > m) { m = f.z; ty = 2; }
        if (f.w > m) { m = f.w; ty = 3; }
    }
    const int lane = threadIdx.x & 31;
    const unsigned lt = (1u << lane) - 1u;
    #pragma unroll
    for (int t = 0; t < TTYPES; t++) {
        unsigned m = __ballot_sync(0xffffffffu, v && ty == t);
        if (m == 0u) continue;
        int leader = __ffs(m) - 1;
        int base = 0;
        if (lane == leader) base = atomicAdd(&g_counts[t], __popc(m));
        base = __shfl_sync(0xffffffffu, base, leader);
        if (v && ty == t) g_idx[t * BUCKET_CAP + base + __popc(m & lt)] = i;
    }
}

// ---------------- kernel 2: weight prep (transpose + split, padded stride) --
// W1 tile c:    B[n][k] = W1[k][c*128+n]
// W2 tile(t,c): B[n][k] = W2[c*128+k][t*128+n]
__global__ void prep_weights(const float* __restrict__ W1, const float* __restrict__ W2) {
    int id = blockIdx.x * blockDim.x + threadIdx.x;   // (tile, n, k-group of 8)
    if (id >= 20 * 128 * 16) return;
    const int tile = id >> 11;
    const int rem  = id & 2047;
    const int n    = rem >> 4;
    const int k0   = (rem & 15) * 8;
    const float* src;
    __nv_bfloat16 *dh, *dl;
    if (tile < 4) {
        src = W1 + (size_t)k0 * HID + tile * 128 + n;
        dh = g_w1t_hi + tile * TILE_ELEM;
        dl = g_w1t_lo + tile * TILE_ELEM;
    } else {
        const int tc = tile - 4;                      // t*4 + c
        const int t = tc >> 2, c = tc & 3;
        src = W2 + (size_t)(c * 128 + k0) * HID + t * 128 + n;
        dh = g_w2t_hi + tc * TILE_ELEM;
        dl = g_w2t_lo + tc * TILE_ELEM;
    }
    uint32_t hw[4], lw[4];
    #pragma unroll
    for (int m = 0; m < 4; m++)
        pack2(src[(size_t)(2 * m) * HID], src[(size_t)(2 * m + 1) * HID], hw[m], lw[m]);
    const int e = n * 136 + k0;                        // 16B-aligned (k0 mult of 8)
    *(uint4*)((char*)dh + e * 2) = make_uint4(hw[0], hw[1], hw[2], hw[3]);
    *(uint4*)((char*)dl + e * 2) = make_uint4(lw[0], lw[1], lw[2], lw[3]);
}

// ---------------- kernel 3: fused MLP, mma.sync 3xBF16 split ----------------
__global__ __launch_bounds__(NTHREADS, 1)
void mlp_mma_kernel(const float* __restrict__ nf,
                    const float* __restrict__ b1,
                    const float* __restrict__ b2,
                    float* __restrict__ out,
                    int ntot)
{
    const int bty = blockIdx.x & 3;        // node type
    const int j   = blockIdx.x >> 2;       // tile within bucket
    const int cnt = g_counts[bty];
    if (j * MROWS >= cnt) return;

    extern __shared__ char smem[];
    int* gidx_s = (int*)(smem + SM_GIDX);
    uint32_t* Xh = (uint32_t*)(smem + SM_X_HI);
    uint32_t* Xl = (uint32_t*)(smem + SM_X_LO);
    uint32_t* Wh = (uint32_t*)(smem + SM_W_HI);
    uint32_t* Wl = (uint32_t*)(smem + SM_W_LO);
    uint32_t* Hh = (uint32_t*)(smem + SM_H_HI);
    uint32_t* Hl = (uint32_t*)(smem + SM_H_LO);
    const uint32_t sb = smem_u32(smem);

    const int tid = threadIdx.x;
    const int wid = tid >> 5, lid = tid & 31;
    const int g = lid >> 2, t4 = lid & 3;    // mma quad layout
    const int wm = wid >> 1, wn = wid & 1;   // warp grid 4(M) x 2(N)
    const int r0 = wm * 32;                  // warp row base
    const int n0 = wn * 64;                  // warp col base within 128

    // ---- stage X: gather 128 rows, split, padded smem ----
    {
        const int row = tid >> 1, half = tid & 1;
        const int p = j * MROWS + row;
        const int gi = (p < cnt) ? g_idx[bty * BUCKET_CAP + p] : -1;
        if (half == 0) gidx_s[row] = gi;
        const float* src = nf + (size_t)(gi < 0 ? 0 : gi) * FIN + TTYPES + half * 64;
        #pragma unroll
        for (int q = 0; q < 8; q++) {
            float f[8];
            if (gi >= 0) {
                float4 f0 = *(const float4*)(src + q * 8);
                float4 f1 = *(const float4*)(src + q * 8 + 4);
                f[0]=f0.x; f[1]=f0.y; f[2]=f0.z; f[3]=f0.w;
                f[4]=f1.x; f[5]=f1.y; f[6]=f1.z; f[7]=f1.w;
            } else {
                #pragma unroll
                for (int m = 0; m < 8; m++) f[m] = 0.0f;
            }
            uint32_t hw[4], lw[4];
            #pragma unroll
            for (int m = 0; m < 4; m++) pack2(f[2*m], f[2*m+1], hw[m], lw[m]);
            const int w = row * TW + half * 32 + q * 4;   // word index, 16B aligned
            *(uint4*)(Xh + w) = make_uint4(hw[0], hw[1], hw[2], hw[3]);
            *(uint4*)(Xl + w) = make_uint4(lw[0], lw[1], lw[2], lw[3]);
        }
    }

    // persistent GEMM2 accumulators: 2 m-tiles x 8 n-tiles x 4
    float acc2[2][8][4];
    #pragma unroll
    for (int mt = 0; mt < 2; mt++)
        #pragma unroll
        for (int nt = 0; nt < 8; nt++)
            #pragma unroll
            for (int e = 0; e < 4; e++) acc2[mt][nt][e] = 0.0f;

    #pragma unroll 1
    for (int c = 0; c < 4; c++) {
        // ---- stage W1 chunk tile ----
        {
            const char* gh = (const char*)g_w1t_hi + c * TILE_B;
            const char* gl = (const char*)g_w1t_lo + c * TILE_B;
            for (int o = tid * 16; o < TILE_B; o += NTHREADS * 16) {
                cpa16(sb + SM_W_HI + o, gh + o);
                cpa16(sb + SM_W_LO + o, gl + o);
            }
            CPA_COMMIT_WAIT();
        }
        __syncthreads();   // W1 + (first iter) X visible

        // ---- GEMM1: acc1 = Xsplit @ W1c ----
        float acc1[2][8][4];
        #pragma unroll
        for (int mt = 0; mt < 2; mt++)
            #pragma unroll
            for (int nt = 0; nt < 8; nt++)
                #pragma unroll
                for (int e = 0; e < 4; e++) acc1[mt][nt][e] = 0.0f;

        #pragma unroll 1
        for (int ks = 0; ks < 8; ks++) {
            uint32_t ah[2][4], al[2][4];
            #pragma unroll
            for (int mt = 0; mt < 2; mt++) {
                const int ba = (r0 + mt * 16 + g) * TW + ks * 8 + t4;
                ah[mt][0]=Xh[ba];     ah[mt][1]=Xh[ba+8*TW];
                ah[mt][2]=Xh[ba+4];   ah[mt][3]=Xh[ba+8*TW+4];
                al[mt][0]=Xl[ba];     al[mt][1]=Xl[ba+8*TW];
                al[mt][2]=Xl[ba+4];   al[mt][3]=Xl[ba+8*TW+4];
            }
            uint32_t bh[8][2], bl[8][2];
            #pragma unroll
            for (int nt = 0; nt < 8; nt++) {
                const int bb = (n0 + nt * 8 + g) * TW + ks * 8 + t4;
                bh[nt][0]=Wh[bb]; bh[nt][1]=Wh[bb+4];
                bl[nt][0]=Wl[bb]; bl[nt][1]=Wl[bb+4];
            }
            #pragma unroll
            for (int mt = 0; mt < 2; mt++)
                #pragma unroll
                for (int nt = 0; nt < 8; nt++) {
                    mma_bf16(acc1[mt][nt], ah[mt], bh[nt]);
                    mma_bf16(acc1[mt][nt], ah[mt], bl[nt]);
                    mma_bf16(acc1[mt][nt], al[mt], bh[nt]);
                }
        }

        // ---- epilogue: bias + exact GELU + split -> H ----
        #pragma unroll
        for (int mt = 0; mt < 2; mt++)
            #pragma unroll
            for (int nt = 0; nt < 8; nt++) {
                const int jcol = c * 128 + n0 + nt * 8 + t4 * 2;
                const float2 bb = *(const float2*)(b1 + jcol);
                const int kw = wn * 32 + nt * 4 + t4;      // H word within row
                const int row0 = r0 + mt * 16 + g;
                float v0 = acc1[mt][nt][0] + bb.x;
                float v1 = acc1[mt][nt][1] + bb.y;
                float v2 = acc1[mt][nt][2] + bb.x;
                float v3 = acc1[mt][nt][3] + bb.y;
                float g0 = v0 * normcdff(v0), g1 = v1 * normcdff(v1);
                float g2 = v2 * normcdff(v2), g3 = v3 * normcdff(v3);
                uint32_t hi, lo;
                pack2(g0, g1, hi, lo);
                Hh[row0 * TW + kw] = hi;  Hl[row0 * TW + kw] = lo;
                pack2(g2, g3, hi, lo);
                Hh[(row0 + 8) * TW + kw] = hi;  Hl[(row0 + 8) * TW + kw] = lo;
            }
        __syncthreads();   // H complete; GEMM1 W reads done

        // ---- stage W2 tile (type, chunk) ----
        {
            const char* gh = (const char*)g_w2t_hi + (bty * 4 + c) * TILE_B;
            const char* gl = (const char*)g_w2t_lo + (bty * 4 + c) * TILE_B;
            for (int o = tid * 16; o < TILE_B; o += NTHREADS * 16) {
                cpa16(sb + SM_W_HI + o, gh + o);
                cpa16(sb + SM_W_LO + o, gl + o);
            }
            CPA_COMMIT_WAIT();
        }
        __syncthreads();

        // ---- GEMM2: acc2 += Hsplit @ W2tc ----
        #pragma unroll 1
        for (int ks = 0; ks < 8; ks++) {
            uint32_t ah[2][4], al[2][4];
            #pragma unroll
            for (int mt = 0; mt < 2; mt++) {
                const int ba = (r0 + mt * 16 + g) * TW + ks * 8 + t4;
                ah[mt][0]=Hh[ba];     ah[mt][1]=Hh[ba+8*TW];
                ah[mt][2]=Hh[ba+4];   ah[mt][3]=Hh[ba+8*TW+4];
                al[mt][0]=Hl[ba];     al[mt][1]=Hl[ba+8*TW];
                al[mt][2]=Hl[ba+4];   al[mt][3]=Hl[ba+8*TW+4];
            }
            uint32_t bh[8][2], bl[8][2];
            #pragma unroll
            for (int nt = 0; nt < 8; nt++) {
                const int bb = (n0 + nt * 8 + g) * TW + ks * 8 + t4;
                bh[nt][0]=Wh[bb]; bh[nt][1]=Wh[bb+4];
                bl[nt][0]=Wl[bb]; bl[nt][1]=Wl[bb+4];
            }
            #pragma unroll
            for (int mt = 0; mt < 2; mt++)
                #pragma unroll
                for (int nt = 0; nt < 8; nt++) {
                    mma_bf16(acc2[mt][nt], ah[mt], bh[nt]);
                    mma_bf16(acc2[mt][nt], ah[mt], bl[nt]);
                    mma_bf16(acc2[mt][nt], al[mt], bh[nt]);
                }
        }
        __syncthreads();   // GEMM2 W/H reads done before next chunk overwrites
    }

    // ---- final: bias + scatter store ----
    #pragma unroll
    for (int mt = 0; mt < 2; mt++)
        #pragma unroll
        for (int nt = 0; nt < 8; nt++) {
            const int jcol = n0 + nt * 8 + t4 * 2;
            const float2 bb = *(const float2*)(b2 + bty * 128 + jcol);
            const int row0 = r0 + mt * 16 + g;
            const int gi0 = gidx_s[row0];
            const int gi1 = gidx_s[row0 + 8];
            if (gi0 >= 0) {
                float2 o = make_float2(acc2[mt][nt][0] + bb.x, acc2[mt][nt][1] + bb.y);
                *(float2*)(out + (size_t)gi0 * D_OUT + jcol) = o;
            }
            if (gi1 >= 0) {
                float2 o = make_float2(acc2[mt][nt][2] + bb.x, acc2[mt][nt][3] + bb.y);
                *(float2*)(out + (size_t)gi1 * D_OUT + jcol) = o;
            }
        }
}

// ---------------- host launcher ----------------
extern "C" void kernel_launch(void* const* d_in, const int* in_sizes, int n_in,
                              void* d_out, int out_size)
{
    const float* nf = (const float*)d_in[0];
    const float* W1 = (const float*)d_in[1];
    const float* b1 = (const float*)d_in[2];
    const float* W2 = (const float*)d_in[3];
    const float* b2 = (const float*)d_in[4];
    float* out = (float*)d_out;

    const int ntot   = in_sizes[0] / FIN;
    const int ntiles = (ntot + MROWS - 1) / MROWS;

    cudaFuncSetAttribute(mlp_mma_kernel,
                         cudaFuncAttributeMaxDynamicSharedMemorySize, SM_TOTAL);

    zero_kernel<<<1, 32>>>();
    bucket_kernel<<<(ntot + 255) / 256, 256>>>(nf, ntot);
    prep_weights<<<(20 * 128 * 16 + 255) / 256, 256>>>(W1, W2);
    mlp_mma_kernel<<<4 * ntiles, NTHREADS, SM_TOTAL>>>(nf, b1, b2, out, ntot);
}

// round 8
// speedup vs baseline: 4.2683x; 1.0343x over previous
#include <cuda_runtime.h>
#include <cuda_bf16.h>
#include <stdint.h>

#define TTYPES   4
#define D_OUT    128
#define FIN      132
#define HID      512
#define MROWS    128
#define NTHREADS 256
#define BUCKET_CAP 262144

#define TW        68            // X/H row stride in words (136 bf16 = 128+8 pad)
#define XH_B      34816         // one X or H buffer (hi or lo): 128*136*2 bytes

#define WHALF_ROWW 36           // W half-tile row stride in words (72 bf16)
#define WHALF_ELEM 9216         // 128 * 72 bf16
#define WHALF_B    18432        // bytes per half (hi or lo)
#define WBUF_B     36864        // hi + lo

// ---------------- device scratch (static: allocation-free) ----------------
__device__ __nv_bfloat16 g_w1t_hi[4 * 2 * WHALF_ELEM];
__device__ __nv_bfloat16 g_w1t_lo[4 * 2 * WHALF_ELEM];
__device__ __nv_bfloat16 g_w2t_hi[16 * 2 * WHALF_ELEM];
__device__ __nv_bfloat16 g_w2t_lo[16 * 2 * WHALF_ELEM];
__device__ int g_counts[TTYPES];
__device__ int g_idx[TTYPES * BUCKET_CAP];

// ---------------- smem layout (bytes) ----------------
#define SM_GIDX  0                       // 128 ints
#define SM_X_HI  512
#define SM_X_LO  (SM_X_HI + XH_B)
#define SM_W0    (SM_X_LO + XH_B)        // two W half-buffers (double buffer)
#define SM_W1    (SM_W0 + WBUF_B)
#define SM_H_HI  (SM_W1 + WBUF_B)
#define SM_H_LO  (SM_H_HI + XH_B)
#define SM_TOTAL (SM_H_LO + XH_B)        // 213504 B = 208.5 KB < 227 KB cap

// ---------------- helpers ----------------
__device__ __forceinline__ void mma_bf16(float* c, const uint32_t* a, const uint32_t* b) {
    asm volatile(
        "mma.sync.aligned.m16n8k16.row.col.f32.bf16.bf16.f32 "
        "{%0,%1,%2,%3}, {%4,%5,%6,%7}, {%8,%9}, {%0,%1,%2,%3};"
        : "+f"(c[0]), "+f"(c[1]), "+f"(c[2]), "+f"(c[3])
        : "r"(a[0]), "r"(a[1]), "r"(a[2]), "r"(a[3]), "r"(b[0]), "r"(b[1]));
}
__device__ __forceinline__ uint32_t smem_u32(const void* p) {
    uint32_t a;
    asm("{ .reg .u64 t; cvta.to.shared.u64 t, %1; cvt.u32.u64 %0, t; }"
        : "=r"(a) : "l"(p));
    return a;
}
__device__ __forceinline__ void cpa16(uint32_t s, const void* g) {
    asm volatile("cp.async.cg.shared.global [%0], [%1], 16;" :: "r"(s), "l"(g));
}
#define CPA_COMMIT() asm volatile("cp.async.commit_group;" ::: "memory")
#define CPA_WAIT(n)  asm volatile("cp.async.wait_group %0;" :: "n"(n) : "memory")

__device__ __forceinline__ void split_bf16(float v, unsigned short& h, unsigned short& l) {
    __nv_bfloat16 hb = __float2bfloat16(v);
    h = __bfloat16_as_ushort(hb);
    l = __bfloat16_as_ushort(__float2bfloat16(v - __bfloat162float(hb)));
}
__device__ __forceinline__ void pack2(float a, float b, uint32_t& hi, uint32_t& lo) {
    unsigned short ha, la, hb, lb;
    split_bf16(a, ha, la); split_bf16(b, hb, lb);
    hi = (uint32_t)ha | ((uint32_t)hb << 16);
    lo = (uint32_t)la | ((uint32_t)lb << 16);
}

// ---------------- kernel 0 / 1: counters + bucketing ----------------
__global__ void zero_kernel() {
    if (threadIdx.x < TTYPES) g_counts[threadIdx.x] = 0;
}
__global__ void bucket_kernel(const float* __restrict__ nf, int ntot) {
    int i = blockIdx.x * blockDim.x + threadIdx.x;
    bool v = i < ntot;
    int ty = 0;
    if (v) {
        float4 f = *(const float4*)(nf + (size_t)i * FIN);
        float m = f.x;
        if (f.y > m) { m = f.y; ty = 1; }
        if (f.z > m) { m = f.z; ty = 2; }
        if (f.w > m) { m = f.w; ty = 3; }
    }
    const int lane = threadIdx.x & 31;
    const unsigned lt = (1u << lane) - 1u;
    #pragma unroll
    for (int t = 0; t < TTYPES; t++) {
        unsigned m = __ballot_sync(0xffffffffu, v && ty == t);
        if (m == 0u) continue;
        int leader = __ffs(m) - 1;
        int base = 0;
        if (lane == leader) base = atomicAdd(&g_counts[t], __popc(m));
        base = __shfl_sync(0xffffffffu, base, leader);
        if (v && ty == t) g_idx[t * BUCKET_CAP + base + __popc(m & lt)] = i;
    }
}

// ---------------- kernel 2: weight prep (transpose + split into K-halves) ---
// W1 tile c:    B[n][k] = W1[k][c*128+n], k in 0..127
// W2 tile(t,c): B[n][k] = W2[c*128+k][t*128+n]
// stored as [tile][half(k>>6)][n][72(=64+8 pad)]
__global__ void prep_weights(const float* __restrict__ W1, const float* __restrict__ W2) {
    int id = blockIdx.x * blockDim.x + threadIdx.x;   // (tile, n, k-group of 8)
    if (id >= 20 * 128 * 16) return;
    const int tile = id >> 11;
    const int rem  = id & 2047;
    const int n    = rem >> 4;
    const int k0   = (rem & 15) * 8;
    const int half = k0 >> 6, kl = k0 & 63;
    const float* src;
    __nv_bfloat16 *dh, *dl;
    if (tile < 4) {
        src = W1 + (size_t)k0 * HID + tile * 128 + n;
        dh = g_w1t_hi + (tile * 2 + half) * WHALF_ELEM;
        dl = g_w1t_lo + (tile * 2 + half) * WHALF_ELEM;
    } else {
        const int tc = tile - 4;                      // t*4 + c
        const int t = tc >> 2, c = tc & 3;
        src = W2 + (size_t)(c * 128 + k0) * HID + t * 128 + n;
        dh = g_w2t_hi + (tc * 2 + half) * WHALF_ELEM;
        dl = g_w2t_lo + (tc * 2 + half) * WHALF_ELEM;
    }
    uint32_t hw[4], lw[4];
    #pragma unroll
    for (int m = 0; m < 4; m++)
        pack2(src[(size_t)(2 * m) * HID], src[(size_t)(2 * m + 1) * HID], hw[m], lw[m]);
    const int e = n * 72 + kl;                         // 16B aligned (kl mult of 8)
    *(uint4*)((char*)dh + e * 2) = make_uint4(hw[0], hw[1], hw[2], hw[3]);
    *(uint4*)((char*)dl + e * 2) = make_uint4(lw[0], lw[1], lw[2], lw[3]);
}

// one GEMM half-phase: 4 k-steps of 16, 2x8 mma tiles, 3-way bf16 split
__device__ __forceinline__ void gemm_half(
    float (*acc)[8][4],
    const uint32_t* __restrict__ Ah, const uint32_t* __restrict__ Al,
    const uint32_t* __restrict__ Bh, const uint32_t* __restrict__ Bl,
    int r0, int n0, int g, int t4, int kofs)
{
    #pragma unroll 1
    for (int ks = 0; ks < 4; ks++) {
        uint32_t ah[2][4], al[2][4];
        #pragma unroll
        for (int mt = 0; mt < 2; mt++) {
            const int ba = (r0 + mt * 16 + g) * TW + kofs + ks * 8 + t4;
            ah[mt][0]=Ah[ba];     ah[mt][1]=Ah[ba+8*TW];
            ah[mt][2]=Ah[ba+4];   ah[mt][3]=Ah[ba+8*TW+4];
            al[mt][0]=Al[ba];     al[mt][1]=Al[ba+8*TW];
            al[mt][2]=Al[ba+4];   al[mt][3]=Al[ba+8*TW+4];
        }
        uint32_t bh[8][2], bl[8][2];
        #pragma unroll
        for (int nt = 0; nt < 8; nt++) {
            const int bb = (n0 + nt * 8 + g) * WHALF_ROWW + ks * 8 + t4;
            bh[nt][0]=Bh[bb]; bh[nt][1]=Bh[bb+4];
            bl[nt][0]=Bl[bb]; bl[nt][1]=Bl[bb+4];
        }
        #pragma unroll
        for (int mt = 0; mt < 2; mt++)
            #pragma unroll
            for (int nt = 0; nt < 8; nt++) {
                mma_bf16(acc[mt][nt], ah[mt], bh[nt]);
                mma_bf16(acc[mt][nt], ah[mt], bl[nt]);
                mma_bf16(acc[mt][nt], al[mt], bh[nt]);
            }
    }
}

// ---------------- kernel 3: fused MLP, pipelined weight staging ----------------
__global__ __launch_bounds__(NTHREADS, 1)
void mlp_mma_kernel(const float* __restrict__ nf,
                    const float* __restrict__ b1,
                    const float* __restrict__ b2,
                    float* __restrict__ out,
                    int ntot)
{
    const int bty = blockIdx.x & 3;
    const int j   = blockIdx.x >> 2;
    const int cnt = g_counts[bty];
    if (j * MROWS >= cnt) return;

    extern __shared__ char smem[];
    int* gidx_s = (int*)(smem + SM_GIDX);
    uint32_t* Xh = (uint32_t*)(smem + SM_X_HI);
    uint32_t* Xl = (uint32_t*)(smem + SM_X_LO);
    uint32_t* Hh = (uint32_t*)(smem + SM_H_HI);
    uint32_t* Hl = (uint32_t*)(smem + SM_H_LO);
    const uint32_t sb = smem_u32(smem);

    const int tid = threadIdx.x;
    const int wid = tid >> 5, lid = tid & 31;
    const int g = lid >> 2, t4 = lid & 3;
    const int wm = wid >> 1, wn = wid & 1;
    const int r0 = wm * 32;
    const int n0 = wn * 64;

    // stage issuer: stage s of 16 -> c = s>>2, phase t = s&3 (W1h0,W1h1,W2h0,W2h1)
    auto issue_stage = [&](int s) {
        const int c = s >> 2, t = s & 3;
        const __nv_bfloat16 *sh, *sl;
        if (t < 2) {
            sh = g_w1t_hi + (c * 2 + t) * WHALF_ELEM;
            sl = g_w1t_lo + (c * 2 + t) * WHALF_ELEM;
        } else {
            const int tc = bty * 4 + c;
            sh = g_w2t_hi + (tc * 2 + (t - 2)) * WHALF_ELEM;
            sl = g_w2t_lo + (tc * 2 + (t - 2)) * WHALF_ELEM;
        }
        const uint32_t dst = sb + SM_W0 + (uint32_t)(s & 1) * WBUF_B;
        for (int o = tid * 16; o < WHALF_B; o += NTHREADS * 16) {
            cpa16(dst + o,           (const char*)sh + o);
            cpa16(dst + WHALF_B + o, (const char*)sl + o);
        }
        CPA_COMMIT();
    };

    // prime pipeline: stages 0,1 in flight while X stages
    issue_stage(0);
    issue_stage(1);

    // ---- stage X: gather 128 rows, split, padded smem ----
    {
        const int row = tid >> 1, half = tid & 1;
        const int p = j * MROWS + row;
        const int gi = (p < cnt) ? g_idx[bty * BUCKET_CAP + p] : -1;
        if (half == 0) gidx_s[row] = gi;
        const float* src = nf + (size_t)(gi < 0 ? 0 : gi) * FIN + TTYPES + half * 64;
        #pragma unroll
        for (int q = 0; q < 8; q++) {
            float f[8];
            if (gi >= 0) {
                float4 f0 = *(const float4*)(src + q * 8);
                float4 f1 = *(const float4*)(src + q * 8 + 4);
                f[0]=f0.x; f[1]=f0.y; f[2]=f0.z; f[3]=f0.w;
                f[4]=f1.x; f[5]=f1.y; f[6]=f1.z; f[7]=f1.w;
            } else {
                #pragma unroll
                for (int m = 0; m < 8; m++) f[m] = 0.0f;
            }
            uint32_t hw[4], lw[4];
            #pragma unroll
            for (int m = 0; m < 4; m++) pack2(f[2*m], f[2*m+1], hw[m], lw[m]);
            const int w = row * TW + half * 32 + q * 4;
            *(uint4*)(Xh + w) = make_uint4(hw[0], hw[1], hw[2], hw[3]);
            *(uint4*)(Xl + w) = make_uint4(lw[0], lw[1], lw[2], lw[3]);
        }
    }
    CPA_WAIT(1);        // stage 0 landed (stage 1 may still fly)
    __syncthreads();    // publish X + stage 0

    float acc2[2][8][4];
    #pragma unroll
    for (int mt = 0; mt < 2; mt++)
        #pragma unroll
        for (int nt = 0; nt < 8; nt++)
            #pragma unroll
            for (int e = 0; e < 4; e++) acc2[mt][nt][e] = 0.0f;

    int s = 0;
    // phase-end: wait next stage, publish, refill freed buffer with stage s+2
    auto advance = [&]() {
        CPA_WAIT(0);
        __syncthreads();
        s++;
        if (s + 1 < 16) issue_stage(s + 1);
    };

    #pragma unroll 1
    for (int c = 0; c < 4; c++) {
        const uint32_t* B0h;
        const uint32_t* B0l;

        float acc1[2][8][4];
        #pragma unroll
        for (int mt = 0; mt < 2; mt++)
            #pragma unroll
            for (int nt = 0; nt < 8; nt++)
                #pragma unroll
                for (int e = 0; e < 4; e++) acc1[mt][nt][e] = 0.0f;

        // phase W1h0
        B0h = (const uint32_t*)(smem + SM_W0 + (s & 1) * WBUF_B);
        B0l = B0h + WHALF_B / 4;
        gemm_half(acc1, Xh, Xl, B0h, B0l, r0, n0, g, t4, 0);
        advance();

        // phase W1h1 + epilogue
        B0h = (const uint32_t*)(smem + SM_W0 + (s & 1) * WBUF_B);
        B0l = B0h + WHALF_B / 4;
        gemm_half(acc1, Xh, Xl, B0h, B0l, r0, n0, g, t4, 32);
        #pragma unroll
        for (int mt = 0; mt < 2; mt++)
            #pragma unroll
            for (int nt = 0; nt < 8; nt++) {
                const int jcol = c * 128 + n0 + nt * 8 + t4 * 2;
                const float2 bb = *(const float2*)(b1 + jcol);
                const int kw = wn * 32 + nt * 4 + t4;
                const int row0 = r0 + mt * 16 + g;
                float v0 = acc1[mt][nt][0] + bb.x;
                float v1 = acc1[mt][nt][1] + bb.y;
                float v2 = acc1[mt][nt][2] + bb.x;
                float v3 = acc1[mt][nt][3] + bb.y;
                float g0 = v0 * normcdff(v0), g1 = v1 * normcdff(v1);
                float g2 = v2 * normcdff(v2), g3 = v3 * normcdff(v3);
                uint32_t hi, lo;
                pack2(g0, g1, hi, lo);
                Hh[row0 * TW + kw] = hi;  Hl[row0 * TW + kw] = lo;
                pack2(g2, g3, hi, lo);
                Hh[(row0 + 8) * TW + kw] = hi;  Hl[(row0 + 8) * TW + kw] = lo;
            }
        advance();   // publishes H + next weight stage together

        // phase W2h0
        B0h = (const uint32_t*)(smem + SM_W0 + (s & 1) * WBUF_B);
        B0l = B0h + WHALF_B / 4;
        gemm_half(acc2, Hh, Hl, B0h, B0l, r0, n0, g, t4, 0);
        advance();

        // phase W2h1
        B0h = (const uint32_t*)(smem + SM_W0 + (s & 1) * WBUF_B);
        B0l = B0h + WHALF_B / 4;
        gemm_half(acc2, Hh, Hl, B0h, B0l, r0, n0, g, t4, 32);
        advance();
    }

    // ---- final: bias + scatter store ----
    #pragma unroll
    for (int mt = 0; mt < 2; mt++)
        #pragma unroll
        for (int nt = 0; nt < 8; nt++) {
            const int jcol = n0 + nt * 8 + t4 * 2;
            const float2 bb = *(const float2*)(b2 + bty * 128 + jcol);
            const int row0 = r0 + mt * 16 + g;
            const int gi0 = gidx_s[row0];
            const int gi1 = gidx_s[row0 + 8];
            if (gi0 >= 0) {
                float2 o = make_float2(acc2[mt][nt][0] + bb.x, acc2[mt][nt][1] + bb.y);
                *(float2*)(out + (size_t)gi0 * D_OUT + jcol) = o;
            }
            if (gi1 >= 0) {
                float2 o = make_float2(acc2[mt][nt][2] + bb.x, acc2[mt][nt][3] + bb.y);
                *(float2*)(out + (size_t)gi1 * D_OUT + jcol) = o;
            }
        }
}

// ---------------- host launcher ----------------
extern "C" void kernel_launch(void* const* d_in, const int* in_sizes, int n_in,
                              void* d_out, int out_size)
{
    const float* nf = (const float*)d_in[0];
    const float* W1 = (const float*)d_in[1];
    const float* b1 = (const float*)d_in[2];
    const float* W2 = (const float*)d_in[3];
    const float* b2 = (const float*)d_in[4];
    float* out = (float*)d_out;

    const int ntot   = in_sizes[0] / FIN;
    const int ntiles = (ntot + MROWS - 1) / MROWS;

    cudaFuncSetAttribute(mlp_mma_kernel,
                         cudaFuncAttributeMaxDynamicSharedMemorySize, SM_TOTAL);

    zero_kernel<<<1, 32>>>();
    bucket_kernel<<<(ntot + 255) / 256, 256>>>(nf, ntot);
    prep_weights<<<(20 * 128 * 16 + 255) / 256, 256>>>(W1, W2);
    mlp_mma_kernel<<<4 * ntiles, NTHREADS, SM_TOTAL>>>(nf, b1, b2, out, ntot);
}